// round 5
// baseline (speedup 1.0000x reference)
#include <cuda_runtime.h>
#include <cuda_bf16.h>

#define E   300
#define P   5
#define H   200
#define S   256
#define L   34
#define B   8
#define KP  320          // K padded (300 -> 320, 10 chunks of 32)
#define NP  704          // N padded (702 -> 704)
#define M   (B*S)        // 2048
#define FCK (3*E + 2*H)  // 1300

// ---------------- scratch ----------------
__device__ __align__(16) float d_A[M*KP];
__device__ __align__(16) float d_Wall[KP*NP];
__device__ __align__(16) float d_Y[M*NP];
__device__ __align__(16) float d_g[512*H];        // [d][h]
__device__ __align__(16) float d_gB0[S*H];        // [i][h]
__device__ __align__(16) float d_gB255[S*H];      // [i][h]
__device__ __align__(16) float d_poolA[M*2*H];    // zone-0 partial (relu'd)
__device__ __align__(16) float d_poolB[M*2*H];    // zone-1 partial (relu'd)
__device__ __align__(16) float d_fcW2t[L*400];    // [l][c]

// ---------------- packed f32x2 add ----------------
union F2U { float2 f; unsigned long long u; };
__device__ __forceinline__ float2 add2(float2 a, float2 b) {
    F2U ua, ub, uc;
    ua.f = a; ub.f = b;
    asm("add.rn.f32x2 %0, %1, %2;" : "=l"(uc.u) : "l"(ua.u), "l"(ub.u));
    return uc.f;
}
__device__ __forceinline__ float2 max2(float2 a, float2 b) {
    return make_float2(fmaxf(a.x, b.x), fmaxf(a.y, b.y));
}

// ---------------- gather (with inline int-width detection) ----------------
__global__ __launch_bounds__(320) void gather_kernel(const int* in32, const float* word_emb) {
    int row = blockIdx.x;
    int lane = threadIdx.x & 31;
    int hw = in32[2*lane + 1];
    unsigned nz = __ballot_sync(0xffffffffu, hw != 0);
    long long tok = (nz == 0) ? ((const long long*)in32)[row]
                              : (long long)in32[row];
    const float* src = word_emb + tok * E;
    int e = threadIdx.x;
    d_A[row*KP + e] = (e < E) ? src[e] : 0.0f;
}

// ---------------- packW: Wall ----------------
__global__ void packW_kernel(const float* conv_W, const float* fc_W) {
    int e = blockIdx.x;                            // 0..319
    int tid = threadIdx.x;
    for (int c = tid; c < NP; c += 256) {
        float v = 0.0f;
        if (e < E) {
            if (c < 600) {
                int k = c / 200, h = c % 200;
                v = conv_W[h*((E+P)*3) + e*3 + k];
            } else if (c < 702) {
                int cc = c - 600, k = cc / L, l = cc % L;
                v = fc_W[l*FCK + 2*H + k*E + e];
            }
        }
        d_Wall[e*NP + c] = v;
    }
}

// ---------------- packG: fcW2t + g-tables ----------------
__global__ void packG_kernel(const float* conv_W, const float* fc_W, const float* pf_emb) {
    int blk = blockIdx.x;
    int tid = threadIdx.x;
    if (blk == 200) {                              // pack fcW2t[l][c]
        for (int idx = tid; idx < L*400; idx += 256) {
            int l = idx / 400, c = idx % 400;
            d_fcW2t[idx] = fc_W[l*FCK + c];
        }
        return;
    }
    int h = blk;                                   // 0..199
    float w0[P], w1[P], w2[P];
    #pragma unroll
    for (int p = 0; p < P; p++) {
        const float* wp = conv_W + h*(E+P)*3 + (E+p)*3;
        w0[p] = wp[0]; w1[p] = wp[1]; w2[p] = wp[2];
    }
    for (int dd = tid; dd < 512; dd += 256) {
        int d = dd - 256;
        int i0 = abs(d-1); if (i0 > 255) i0 = 255;
        int i1 = abs(d);   if (i1 > 255) i1 = 255;
        int i2 = abs(d+1); if (i2 > 255) i2 = 255;
        float acc = 0.0f;
        #pragma unroll
        for (int p = 0; p < P; p++)
            acc += w0[p]*pf_emb[i0*P+p] + w1[p]*pf_emb[i1*P+p] + w2[p]*pf_emb[i2*P+p];
        d_g[dd*H + h] = acc;
    }
    if (tid >= 1 && tid <= 254) {
        int i = tid;
        float a0 = 0.0f, a255 = 0.0f;
        #pragma unroll
        for (int p = 0; p < P; p++) {
            a0   += w1[p]*pf_emb[i*P+p] + w2[p]*pf_emb[(i-1)*P+p];
            a255 += w0[p]*pf_emb[(254-i >= 0 ? 254-i : i-254)*P+p] + w1[p]*pf_emb[(255-i)*P+p];
        }
        d_gB0[i*H + h]   = a0;
        d_gB255[i*H + h] = a255;
    }
}

// ---------------- bf16 split tensor-core GEMM ----------------
__device__ __forceinline__ unsigned pk2(float a, float b) {
    __nv_bfloat162 t = __floats2bfloat162_rn(a, b);
    return *reinterpret_cast<unsigned*>(&t);
}
__device__ __forceinline__ float bhi(float x) {
    return __bfloat162float(__float2bfloat16(x));
}
__device__ __forceinline__ void mma_bf16(float* d, const unsigned* a, const unsigned* b) {
    asm volatile("mma.sync.aligned.m16n8k16.row.col.f32.bf16.bf16.f32 "
        "{%0,%1,%2,%3},{%4,%5,%6,%7},{%8,%9},{%0,%1,%2,%3};\n"
        : "+f"(d[0]), "+f"(d[1]), "+f"(d[2]), "+f"(d[3])
        : "r"(a[0]), "r"(a[1]), "r"(a[2]), "r"(a[3]), "r"(b[0]), "r"(b[1]));
}

__global__ __launch_bounds__(256, 2) void gemm_kernel() {
    __shared__ unsigned Ah[128][20], Al[128][20];
    __shared__ unsigned Bh[16][72],  Bl[16][72];

    const int t = threadIdx.x, lane = t & 31, warp = t >> 5;
    const int wm = warp >> 1, wn = warp & 1;
    const int mBase = wm * 32, nBase = wn * 32;
    const int r0 = lane >> 2, c0 = lane & 3;

    float acc[2][4][4];
    #pragma unroll
    for (int mi = 0; mi < 2; mi++)
        #pragma unroll
        for (int ni = 0; ni < 4; ni++)
            #pragma unroll
            for (int q = 0; q < 4; q++) acc[mi][ni][q] = 0.0f;

    const float* Ag = d_A + (size_t)blockIdx.x * 128 * KP;
    const float* Bg = d_Wall + blockIdx.y * 64;

    const int am  = t >> 1;
    const int akq = (t & 1) * 16;
    const int bn  = t & 63;
    const int bkp0 = t >> 6;

    float4 av[4];
    float bg0[4], bg1[4];
    #pragma unroll
    for (int q = 0; q < 4; q++)
        av[q] = *(const float4*)(Ag + am*KP + akq + q*4);
    #pragma unroll
    for (int it = 0; it < 4; it++) {
        int kp = bkp0 + it*4;
        bg0[it] = Bg[(2*kp)*NP + bn];
        bg1[it] = Bg[(2*kp+1)*NP + bn];
    }

    for (int ch = 0; ch < 10; ch++) {
        __syncthreads();
        #pragma unroll
        for (int q = 0; q < 4; q++) {
            float x0 = av[q].x, x1 = av[q].y, x2 = av[q].z, x3 = av[q].w;
            float h0 = bhi(x0), h1 = bhi(x1), h2 = bhi(x2), h3 = bhi(x3);
            int p = (t & 1)*8 + q*2;
            Ah[am][p]   = pk2(h0, h1);
            Ah[am][p+1] = pk2(h2, h3);
            Al[am][p]   = pk2(x0-h0, x1-h1);
            Al[am][p+1] = pk2(x2-h2, x3-h3);
        }
        #pragma unroll
        for (int it = 0; it < 4; it++) {
            int kp = bkp0 + it*4;
            float h0 = bhi(bg0[it]), h1 = bhi(bg1[it]);
            Bh[kp][bn] = pk2(h0, h1);
            Bl[kp][bn] = pk2(bg0[it]-h0, bg1[it]-h1);
        }
        __syncthreads();
        if (ch < 9) {
            int kc = (ch + 1) * 32;
            #pragma unroll
            for (int q = 0; q < 4; q++)
                av[q] = *(const float4*)(Ag + am*KP + kc + akq + q*4);
            #pragma unroll
            for (int it = 0; it < 4; it++) {
                int kp = bkp0 + it*4;
                bg0[it] = Bg[(kc + 2*kp)*NP + bn];
                bg1[it] = Bg[(kc + 2*kp + 1)*NP + bn];
            }
        }
        #pragma unroll
        for (int ks = 0; ks < 2; ks++) {
            int p0 = ks*8 + c0;
            unsigned ah[2][4], al[2][4];
            #pragma unroll
            for (int mi = 0; mi < 2; mi++) {
                int mr = mBase + mi*16 + r0;
                ah[mi][0] = Ah[mr][p0];     al[mi][0] = Al[mr][p0];
                ah[mi][1] = Ah[mr+8][p0];   al[mi][1] = Al[mr+8][p0];
                ah[mi][2] = Ah[mr][p0+4];   al[mi][2] = Al[mr][p0+4];
                ah[mi][3] = Ah[mr+8][p0+4]; al[mi][3] = Al[mr+8][p0+4];
            }
            unsigned bh[4][2], bl[4][2];
            #pragma unroll
            for (int ni = 0; ni < 4; ni++) {
                int n = nBase + ni*8 + r0;
                bh[ni][0] = Bh[p0][n];   bl[ni][0] = Bl[p0][n];
                bh[ni][1] = Bh[p0+4][n]; bl[ni][1] = Bl[p0+4][n];
            }
            #pragma unroll
            for (int mi = 0; mi < 2; mi++)
                #pragma unroll
                for (int ni = 0; ni < 4; ni++) {
                    mma_bf16(acc[mi][ni], ah[mi], bh[ni]);
                    mma_bf16(acc[mi][ni], al[mi], bh[ni]);
                    mma_bf16(acc[mi][ni], ah[mi], bl[ni]);
                }
        }
    }
    float* Yg = d_Y + (size_t)(blockIdx.x*128)*NP + blockIdx.y*64;
    #pragma unroll
    for (int mi = 0; mi < 2; mi++) {
        int mr = mBase + mi*16 + r0;
        #pragma unroll
        for (int ni = 0; ni < 4; ni++) {
            int nc = nBase + ni*8 + 2*c0;
            *(float2*)(Yg + mr*NP + nc)     = make_float2(acc[mi][ni][0], acc[mi][ni][1]);
            *(float2*)(Yg + (mr+8)*NP + nc) = make_float2(acc[mi][ni][2], acc[mi][ni][3]);
        }
    }
}

// ---------------- fused ct + max-plus pooling, j-range split in 2 zones ----------------
__device__ __forceinline__ float2 compute_ct(int b, int j, int hp, float2 cb) {
    int row = b*S + j;
    float2 v = add2(cb, *(const float2*)&d_Y[row*NP + 200 + 2*hp]);
    if (j > 0)   v = add2(v, *(const float2*)&d_Y[(row-1)*NP + 2*hp]);
    if (j < S-1) v = add2(v, *(const float2*)&d_Y[(row+1)*NP + 400 + 2*hp]);
    return v;
}

__global__ __launch_bounds__(128) void pool_kernel(const float* conv_b) {
    int hp = blockIdx.x;            // h-pair 0..99
    int b  = blockIdx.y;
    int z  = blockIdx.z;            // j-zone: 0 -> [0,127], 1 -> [128,255]
    __shared__ float2 cts[128];
    __shared__ float2 gs_e[256];    // g[2q][h-pair]
    __shared__ float2 gs_o[256];    // g[2q+1][h-pair]
    int t = threadIdx.x;            // 0..127

    float2 cb = *(const float2*)&conv_b[2*hp];
    cts[t] = compute_ct(b, z*128 + t, hp, cb);
    gs_e[t]     = *(const float2*)&d_g[(2*t)*H + 2*hp];
    gs_e[t+128] = *(const float2*)&d_g[(2*t+256)*H + 2*hp];
    gs_o[t]     = *(const float2*)&d_g[(2*t+1)*H + 2*hp];
    gs_o[t+128] = *(const float2*)&d_g[(2*t+257)*H + 2*hp];
    __syncthreads();

    int i0 = 2*t + 1, i1 = 2*t + 2;
    int ie0 = min(i0, 254), ie1 = min(i1, 254);
    const float NEG = -1e30f;
    float2 mL0, mL1, mR0, mR1, gprev;
    int idx, j, hiP;
    int w = t >> 5;

    if (z == 0) {
        float2 c0v = cts[0];
        mL0 = add2(c0v, *(const float2*)&d_gB0[ie0*H + 2*hp]);
        mL1 = add2(c0v, *(const float2*)&d_gB0[ie1*H + 2*hp]);
        mR0 = make_float2(NEG, NEG); mR1 = mR0;
        gprev = gs_o[127 - t];
        idx = 128 - t;
        j = 1;  hiP = 126;
    } else {
        float2 c255 = cts[127];
        mR0 = add2(c255, *(const float2*)&d_gB255[ie0*H + 2*hp]);
        mR1 = add2(c255, *(const float2*)&d_gB255[ie1*H + 2*hp]);
        mL0 = make_float2(NEG, NEG); mL1 = mL0;
        // head: j = 128 (even), predicated
        float2 c = cts[0];
        float2 go = gs_o[191 - t], ge = gs_e[191 - t];
        float2 v0 = add2(c, go), v1 = add2(c, ge);
        if (128 < i0) mL0 = max2(mL0, v0); else mR0 = max2(mR0, v0);
        if (128 < i1) mL1 = max2(mL1, v1); else mR1 = max2(mR1, v1);
        gprev = go;
        idx = 192 - t;
        j = 129;  hiP = 254;
    }

    const float2* ctp = cts - z*128;          // ctp[j] valid within zone
    int jA = min(64*w, hiP);
    int jB = min(64*w + 64, hiP);

    // phase 1: all-left
    #pragma unroll 2
    for (; j + 1 <= jA; j += 2) {
        float2 c1 = ctp[j],   ga = gs_e[idx];
        mL0 = max2(mL0, add2(c1, ga));
        mL1 = max2(mL1, add2(c1, gprev));
        float2 c2 = ctp[j+1], gb = gs_o[idx];
        mL0 = max2(mL0, add2(c2, gb));
        mL1 = max2(mL1, add2(c2, ga));
        gprev = gb; idx++;
    }
    // phase 2: mixed
    for (; j + 1 <= jB; j += 2) {
        float2 c1 = ctp[j],   ga = gs_e[idx];
        float2 v0 = add2(c1, ga), v1 = add2(c1, gprev);
        if (j < i0) mL0 = max2(mL0, v0); else mR0 = max2(mR0, v0);
        if (j < i1) mL1 = max2(mL1, v1); else mR1 = max2(mR1, v1);
        float2 c2 = ctp[j+1], gb = gs_o[idx];
        float2 u0 = add2(c2, gb), u1 = add2(c2, ga);
        if (j+1 < i0) mL0 = max2(mL0, u0); else mR0 = max2(mR0, u0);
        if (j+1 < i1) mL1 = max2(mL1, u1); else mR1 = max2(mR1, u1);
        gprev = gb; idx++;
    }
    // phase 3: all-right
    #pragma unroll 2
    for (; j + 1 <= hiP; j += 2) {
        float2 c1 = ctp[j],   ga = gs_e[idx];
        mR0 = max2(mR0, add2(c1, ga));
        mR1 = max2(mR1, add2(c1, gprev));
        float2 c2 = ctp[j+1], gb = gs_o[idx];
        mR0 = max2(mR0, add2(c2, gb));
        mR1 = max2(mR1, add2(c2, ga));
        gprev = gb; idx++;
    }

    if (z == 0) {
        // tail: j = 127 (odd), predicated
        float2 c = cts[127], ga = gs_e[idx];
        float2 v0 = add2(c, ga), v1 = add2(c, gprev);
        if (127 < i0) mL0 = max2(mL0, v0); else mR0 = max2(mR0, v0);
        if (127 < i1) mL1 = max2(mL1, v1); else mR1 = max2(mR1, v1);
    }

    float2 zf = make_float2(0.0f, 0.0f);
    float* dst = z ? d_poolB : d_poolA;
    if (t < 127) {
        float* p0 = dst + (b*S + i0)*(2*H) + 2*hp;
        *(float2*)(p0)     = max2(mL0, zf);
        *(float2*)(p0 + H) = max2(mR0, zf);
        float* p1 = dst + (b*S + i1)*(2*H) + 2*hp;
        *(float2*)(p1)     = max2(mL1, zf);
        *(float2*)(p1 + H) = max2(mR1, zf);
    }
}

// ---------------- final logits: warp per (b,s), max of zone partials ----------------
__global__ __launch_bounds__(256) void final_kernel(const float* fc_b, float* out) {
    int gw = (blockIdx.x * 256 + threadIdx.x) >> 5;   // 0..2047 = b*256+s
    int lane = threadIdx.x & 31;
    int s = gw & (S-1);
    float* o = out + gw * L;
    if (s == 0 || s == S-1) {
        o[lane] = 0.0f;
        if (lane < 2) o[lane + 32] = (lane == 1) ? 1.0f : 0.0f;
        return;
    }
    const float* prA = d_poolA + gw * (2*H);
    const float* prB = d_poolB + gw * (2*H);
    const float* Wl = d_fcW2t + lane * 400;
    float a0 = 0.f, a1 = 0.f, a2 = 0.f, a3 = 0.f;
    #pragma unroll 4
    for (int c = 0; c < 400; c += 4) {
        float4 pa = *(const float4*)(prA + c);
        float4 pb = *(const float4*)(prB + c);
        float4 wv = *(const float4*)(Wl + c);
        a0 += fmaxf(pa.x, pb.x) * wv.x;
        a1 += fmaxf(pa.y, pb.y) * wv.y;
        a2 += fmaxf(pa.z, pb.z) * wv.z;
        a3 += fmaxf(pa.w, pb.w) * wv.w;
    }
    float acc0 = (a0 + a1) + (a2 + a3) + fc_b[lane];
    acc0 += d_Y[(gw-1)*NP + 600 + lane]
          + d_Y[gw*NP     + 634 + lane]
          + d_Y[(gw+1)*NP + 668 + lane];
    o[lane] = acc0;

    const float* W32 = d_fcW2t + 32 * 400;
    const float* W33 = d_fcW2t + 33 * 400;
    float r32 = 0.f, r33 = 0.f;
    #pragma unroll
    for (int c = lane; c < 400; c += 32) {
        float p = fmaxf(prA[c], prB[c]);
        r32 += p * W32[c];
        r33 += p * W33[c];
    }
    #pragma unroll
    for (int off = 16; off > 0; off >>= 1) {
        r32 += __shfl_xor_sync(0xFFFFFFFF, r32, off);
        r33 += __shfl_xor_sync(0xFFFFFFFF, r33, off);
    }
    if (lane < 2) {
        float r = (lane == 0) ? r32 : r33;
        r += fc_b[32 + lane]
           + d_Y[(gw-1)*NP + 632 + lane]
           + d_Y[gw*NP     + 666 + lane]
           + d_Y[(gw+1)*NP + 700 + lane];
        o[32 + lane] = r;
    }
}

extern "C" void kernel_launch(void* const* d_in, const int* in_sizes, int n_in,
                              void* d_out, int out_size) {
    const int*   inputs   = (const int*)d_in[0];
    const float* word_emb = (const float*)d_in[1];
    const float* pf_emb   = (const float*)d_in[2];
    const float* conv_W   = (const float*)d_in[3];
    const float* conv_b   = (const float*)d_in[4];
    const float* fc_W     = (const float*)d_in[5];
    const float* fc_b     = (const float*)d_in[6];
    float* out = (float*)d_out;

    gather_kernel<<<M, 320>>>(inputs, word_emb);          // launch 0
    packW_kernel<<<320, 256>>>(conv_W, fc_W);             // launch 1
    packG_kernel<<<201, 256>>>(conv_W, fc_W, pf_emb);     // launch 2

    dim3 ggrid(M/128, NP/64);
    gemm_kernel<<<ggrid, 256>>>();                        // launch 3 (profiled slot)

    dim3 pgrid(H/2, B, 2);
    pool_kernel<<<pgrid, 128>>>(conv_b);                  // launch 4

    final_kernel<<<256, 256>>>(fc_b, out);                // launch 5
}

// round 6
// speedup vs baseline: 1.0244x; 1.0244x over previous
#include <cuda_runtime.h>
#include <cuda_bf16.h>

#define E   300
#define P   5
#define H   200
#define S   256
#define L   34
#define B   8
#define KPP 160          // kpairs per A row (K = 320 padded)
#define NP  704          // N padded (702 -> 704)
#define M   (B*S)        // 2048
#define FCK (3*E + 2*H)  // 1300

// ---------------- scratch ----------------
__device__ __align__(16) unsigned d_Ahp[M*KPP];   // A hi plane, bf16x2 [row][kpair]
__device__ __align__(16) unsigned d_Alp[M*KPP];   // A lo plane
__device__ __align__(16) unsigned d_Whp[KPP*NP];  // W hi plane, bf16x2 [kpair][n]
__device__ __align__(16) unsigned d_Wlp[KPP*NP];  // W lo plane
__device__ __align__(16) float d_Y[M*NP];
__device__ __align__(16) float d_g[512*H];        // [d][h]
__device__ __align__(16) float d_gB0[S*H];        // [i][h]
__device__ __align__(16) float d_gB255[S*H];      // [i][h]
__device__ __align__(16) float d_poolA[M*2*H];    // zone-0 partial (relu'd)
__device__ __align__(16) float d_poolB[M*2*H];    // zone-1 partial (relu'd)
__device__ __align__(16) float d_fcW2t[L*400];    // [l][c]

// ---------------- helpers ----------------
union F2U { float2 f; unsigned long long u; };
__device__ __forceinline__ float2 add2(float2 a, float2 b) {
    F2U ua, ub, uc;
    ua.f = a; ub.f = b;
    asm("add.rn.f32x2 %0, %1, %2;" : "=l"(uc.u) : "l"(ua.u), "l"(ub.u));
    return uc.f;
}
__device__ __forceinline__ float2 max2(float2 a, float2 b) {
    return make_float2(fmaxf(a.x, b.x), fmaxf(a.y, b.y));
}
__device__ __forceinline__ unsigned pk2(float a, float b) {
    __nv_bfloat162 t = __floats2bfloat162_rn(a, b);
    return *reinterpret_cast<unsigned*>(&t);
}
__device__ __forceinline__ float bhi(float x) {
    return __bfloat162float(__float2bfloat16(x));
}
__device__ __forceinline__ void mma_bf16(float* d, const unsigned* a, const unsigned* b) {
    asm volatile("mma.sync.aligned.m16n8k16.row.col.f32.bf16.bf16.f32 "
        "{%0,%1,%2,%3},{%4,%5,%6,%7},{%8,%9},{%0,%1,%2,%3};\n"
        : "+f"(d[0]), "+f"(d[1]), "+f"(d[2]), "+f"(d[3])
        : "r"(a[0]), "r"(a[1]), "r"(a[2]), "r"(a[3]), "r"(b[0]), "r"(b[1]));
}
__device__ __forceinline__ void cpa16(unsigned dst, const void* src) {
    asm volatile("cp.async.ca.shared.global [%0], [%1], 16;\n" :: "r"(dst), "l"(src));
}

// ---------------- prepA: gather token embeddings into split bf16 planes ----------------
__global__ __launch_bounds__(192) void prepA_kernel(const int* in32, const float* word_emb) {
    int row = blockIdx.x;
    int lane = threadIdx.x & 31;
    int hw = in32[2*lane + 1];
    unsigned nz = __ballot_sync(0xffffffffu, hw != 0);
    long long tok = (nz == 0) ? ((const long long*)in32)[row]
                              : (long long)in32[row];
    int p = threadIdx.x;
    if (p >= KPP) return;
    const float* src = word_emb + tok * E;
    float x0 = 0.0f, x1 = 0.0f;
    int e = 2*p;
    if (e < E) {
        x0 = src[e];
        x1 = (e + 1 < E) ? src[e+1] : 0.0f;
    }
    float h0 = bhi(x0), h1 = bhi(x1);
    d_Ahp[row*KPP + p] = pk2(h0, h1);
    d_Alp[row*KPP + p] = pk2(x0 - h0, x1 - h1);
}

// ---------------- prepB: pack W planes + fcW2t + g-tables ----------------
__device__ __forceinline__ float wallv(int e, int c, const float* conv_W, const float* fc_W) {
    if (e >= E) return 0.0f;
    if (c < 600) {
        int k = c / 200, h = c % 200;
        return conv_W[h*((E+P)*3) + e*3 + k];
    }
    if (c < 702) {
        int cc = c - 600, k = cc / L, l = cc % L;
        return fc_W[l*FCK + 2*H + k*E + e];
    }
    return 0.0f;
}

__global__ void prepB_kernel(const float* conv_W, const float* fc_W, const float* pf_emb) {
    int blk = blockIdx.x;
    int tid = threadIdx.x;
    if (blk < 160) {                               // W planes, kpair = blk
        int kp = blk;
        for (int c = tid; c < NP; c += 256) {
            float v0 = wallv(2*kp,     c, conv_W, fc_W);
            float v1 = wallv(2*kp + 1, c, conv_W, fc_W);
            float h0 = bhi(v0), h1 = bhi(v1);
            d_Whp[kp*NP + c] = pk2(h0, h1);
            d_Wlp[kp*NP + c] = pk2(v0 - h0, v1 - h1);
        }
        return;
    }
    if (blk == 160) {                              // fcW2t[l][c]
        for (int idx = tid; idx < L*400; idx += 256) {
            int l = idx / 400, c = idx % 400;
            d_fcW2t[idx] = fc_W[l*FCK + c];
        }
        return;
    }
    int h = blk - 161;                             // 0..199 g-tables
    float w0[P], w1[P], w2[P];
    #pragma unroll
    for (int p = 0; p < P; p++) {
        const float* wp = conv_W + h*(E+P)*3 + (E+p)*3;
        w0[p] = wp[0]; w1[p] = wp[1]; w2[p] = wp[2];
    }
    for (int dd = tid; dd < 512; dd += 256) {
        int d = dd - 256;
        int i0 = abs(d-1); if (i0 > 255) i0 = 255;
        int i1 = abs(d);   if (i1 > 255) i1 = 255;
        int i2 = abs(d+1); if (i2 > 255) i2 = 255;
        float acc = 0.0f;
        #pragma unroll
        for (int p = 0; p < P; p++)
            acc += w0[p]*pf_emb[i0*P+p] + w1[p]*pf_emb[i1*P+p] + w2[p]*pf_emb[i2*P+p];
        d_g[dd*H + h] = acc;
    }
    if (tid >= 1 && tid <= 254) {
        int i = tid;
        float a0 = 0.0f, a255 = 0.0f;
        #pragma unroll
        for (int p = 0; p < P; p++) {
            a0   += w1[p]*pf_emb[i*P+p] + w2[p]*pf_emb[(i-1)*P+p];
            a255 += w0[p]*pf_emb[(254-i >= 0 ? 254-i : i-254)*P+p] + w1[p]*pf_emb[(255-i)*P+p];
        }
        d_gB0[i*H + h]   = a0;
        d_gB255[i*H + h] = a255;
    }
}

// ---------------- GEMM: cp.async double-buffered, no in-loop conversion ----------------
// 128x64 tile, 512 threads (16 warps = 8m x 2n of 16x32 warp tiles), 10 chunks of K=32.
__global__ __launch_bounds__(512, 2) void gemm_kernel() {
    __shared__ unsigned Ah[2][128][20], Al[2][128][20];
    __shared__ unsigned Bh[2][16][72],  Bl[2][16][72];

    const int t = threadIdx.x, lane = t & 31, warp = t >> 5;
    const int wm = warp >> 1, wn = warp & 1;
    const int mBase = wm * 16, nBase = wn * 32;
    const int r0 = lane >> 2, c0 = lane & 3;

    float acc[4][4];
    #pragma unroll
    for (int ni = 0; ni < 4; ni++)
        #pragma unroll
        for (int q = 0; q < 4; q++) acc[ni][q] = 0.0f;

    const unsigned* Agh = d_Ahp + (size_t)blockIdx.x * 128 * KPP;
    const unsigned* Agl = d_Alp + (size_t)blockIdx.x * 128 * KPP;
    const unsigned* Bgh = d_Whp + blockIdx.y * 64;
    const unsigned* Bgl = d_Wlp + blockIdx.y * 64;

    // cp.async work split: A 512 16B-segs/plane (1 per thread per plane),
    // B 256 segs/plane (thread t<256 -> hi, t>=256 -> lo)
    const int am   = t >> 2;            // A row 0..127
    const int aseg = (t & 3) * 4;       // kpair base within chunk
    const int bpl  = t >> 8;            // B plane select
    const int bt   = t & 255;
    const int bk   = bt >> 4;           // B kpair row 0..15
    const int bn4  = (bt & 15) * 4;     // B col base

    unsigned sAh = (unsigned)__cvta_generic_to_shared(&Ah[0][am][aseg]);
    unsigned sAl = (unsigned)__cvta_generic_to_shared(&Al[0][am][aseg]);
    unsigned sB  = bpl ? (unsigned)__cvta_generic_to_shared(&Bl[0][bk][bn4])
                       : (unsigned)__cvta_generic_to_shared(&Bh[0][bk][bn4]);
    const unsigned* Bgp = bpl ? Bgl : Bgh;
    const unsigned A_ST = 128*20*4;     // stage stride bytes
    const unsigned B_ST = 16*72*4;

    // prologue: stage 0
    {
        cpa16(sAh, Agh + am*KPP + aseg);
        cpa16(sAl, Agl + am*KPP + aseg);
        cpa16(sB,  Bgp + bk*NP + bn4);
        asm volatile("cp.async.commit_group;\n");
    }

    #pragma unroll 1
    for (int ch = 0; ch < 10; ch++) {
        int st = ch & 1;
        if (ch < 9) {
            int kc = (ch + 1) * 16;     // kpair offset
            int st1 = st ^ 1;
            cpa16(sAh + st1*A_ST, Agh + am*KPP + kc + aseg);
            cpa16(sAl + st1*A_ST, Agl + am*KPP + kc + aseg);
            cpa16(sB  + st1*B_ST, Bgp + (kc + bk)*NP + bn4);
            asm volatile("cp.async.commit_group;\n");
            asm volatile("cp.async.wait_group 1;\n");
        } else {
            asm volatile("cp.async.wait_group 0;\n");
        }
        __syncthreads();

        #pragma unroll
        for (int ks = 0; ks < 2; ks++) {
            int p0 = ks*8 + c0;
            int mr = mBase + r0;
            unsigned ah[4], al[4];
            ah[0] = Ah[st][mr][p0];     al[0] = Al[st][mr][p0];
            ah[1] = Ah[st][mr+8][p0];   al[1] = Al[st][mr+8][p0];
            ah[2] = Ah[st][mr][p0+4];   al[2] = Al[st][mr][p0+4];
            ah[3] = Ah[st][mr+8][p0+4]; al[3] = Al[st][mr+8][p0+4];
            unsigned bh[4][2], bl[4][2];
            #pragma unroll
            for (int ni = 0; ni < 4; ni++) {
                int n = nBase + ni*8 + r0;
                bh[ni][0] = Bh[st][p0][n];   bl[ni][0] = Bl[st][p0][n];
                bh[ni][1] = Bh[st][p0+4][n]; bl[ni][1] = Bl[st][p0+4][n];
            }
            #pragma unroll
            for (int ni = 0; ni < 4; ni++) {
                mma_bf16(acc[ni], ah, bh[ni]);
                mma_bf16(acc[ni], al, bh[ni]);
                mma_bf16(acc[ni], ah, bl[ni]);
            }
        }
        __syncthreads();
    }

    float* Yg = d_Y + (size_t)(blockIdx.x*128)*NP + blockIdx.y*64;
    int mr = mBase + r0;
    #pragma unroll
    for (int ni = 0; ni < 4; ni++) {
        int nc = nBase + ni*8 + 2*c0;
        *(float2*)(Yg + mr*NP + nc)     = make_float2(acc[ni][0], acc[ni][1]);
        *(float2*)(Yg + (mr+8)*NP + nc) = make_float2(acc[ni][2], acc[ni][3]);
    }
}

// ---------------- fused ct + max-plus pooling, j-range split in 2 zones ----------------
__device__ __forceinline__ float2 compute_ct(int b, int j, int hp, float2 cb) {
    int row = b*S + j;
    float2 v = add2(cb, *(const float2*)&d_Y[row*NP + 200 + 2*hp]);
    if (j > 0)   v = add2(v, *(const float2*)&d_Y[(row-1)*NP + 2*hp]);
    if (j < S-1) v = add2(v, *(const float2*)&d_Y[(row+1)*NP + 400 + 2*hp]);
    return v;
}

__global__ __launch_bounds__(128) void pool_kernel(const float* conv_b) {
    int hp = blockIdx.x;            // h-pair 0..99
    int b  = blockIdx.y;
    int z  = blockIdx.z;            // j-zone: 0 -> [0,127], 1 -> [128,255]
    __shared__ float2 cts[128];
    __shared__ float2 gs_e[256];
    __shared__ float2 gs_o[256];
    int t = threadIdx.x;

    float2 cb = *(const float2*)&conv_b[2*hp];
    cts[t] = compute_ct(b, z*128 + t, hp, cb);
    gs_e[t]     = *(const float2*)&d_g[(2*t)*H + 2*hp];
    gs_e[t+128] = *(const float2*)&d_g[(2*t+256)*H + 2*hp];
    gs_o[t]     = *(const float2*)&d_g[(2*t+1)*H + 2*hp];
    gs_o[t+128] = *(const float2*)&d_g[(2*t+257)*H + 2*hp];
    __syncthreads();

    int i0 = 2*t + 1, i1 = 2*t + 2;
    int ie0 = min(i0, 254), ie1 = min(i1, 254);
    const float NEG = -1e30f;
    float2 mL0, mL1, mR0, mR1, gprev;
    int idx, j, hiP;
    int w = t >> 5;

    if (z == 0) {
        float2 c0v = cts[0];
        mL0 = add2(c0v, *(const float2*)&d_gB0[ie0*H + 2*hp]);
        mL1 = add2(c0v, *(const float2*)&d_gB0[ie1*H + 2*hp]);
        mR0 = make_float2(NEG, NEG); mR1 = mR0;
        gprev = gs_o[127 - t];
        idx = 128 - t;
        j = 1;  hiP = 126;
    } else {
        float2 c255 = cts[127];
        mR0 = add2(c255, *(const float2*)&d_gB255[ie0*H + 2*hp]);
        mR1 = add2(c255, *(const float2*)&d_gB255[ie1*H + 2*hp]);
        mL0 = make_float2(NEG, NEG); mL1 = mL0;
        float2 c = cts[0];
        float2 go = gs_o[191 - t], ge = gs_e[191 - t];
        float2 v0 = add2(c, go), v1 = add2(c, ge);
        if (128 < i0) mL0 = max2(mL0, v0); else mR0 = max2(mR0, v0);
        if (128 < i1) mL1 = max2(mL1, v1); else mR1 = max2(mR1, v1);
        gprev = go;
        idx = 192 - t;
        j = 129;  hiP = 254;
    }

    const float2* ctp = cts - z*128;
    int jA = min(64*w, hiP);
    int jB = min(64*w + 64, hiP);

    #pragma unroll 2
    for (; j + 1 <= jA; j += 2) {
        float2 c1 = ctp[j],   ga = gs_e[idx];
        mL0 = max2(mL0, add2(c1, ga));
        mL1 = max2(mL1, add2(c1, gprev));
        float2 c2 = ctp[j+1], gb = gs_o[idx];
        mL0 = max2(mL0, add2(c2, gb));
        mL1 = max2(mL1, add2(c2, ga));
        gprev = gb; idx++;
    }
    for (; j + 1 <= jB; j += 2) {
        float2 c1 = ctp[j],   ga = gs_e[idx];
        float2 v0 = add2(c1, ga), v1 = add2(c1, gprev);
        if (j < i0) mL0 = max2(mL0, v0); else mR0 = max2(mR0, v0);
        if (j < i1) mL1 = max2(mL1, v1); else mR1 = max2(mR1, v1);
        float2 c2 = ctp[j+1], gb = gs_o[idx];
        float2 u0 = add2(c2, gb), u1 = add2(c2, ga);
        if (j+1 < i0) mL0 = max2(mL0, u0); else mR0 = max2(mR0, u0);
        if (j+1 < i1) mL1 = max2(mL1, u1); else mR1 = max2(mR1, u1);
        gprev = gb; idx++;
    }
    #pragma unroll 2
    for (; j + 1 <= hiP; j += 2) {
        float2 c1 = ctp[j],   ga = gs_e[idx];
        mR0 = max2(mR0, add2(c1, ga));
        mR1 = max2(mR1, add2(c1, gprev));
        float2 c2 = ctp[j+1], gb = gs_o[idx];
        mR0 = max2(mR0, add2(c2, gb));
        mR1 = max2(mR1, add2(c2, ga));
        gprev = gb; idx++;
    }

    if (z == 0) {
        float2 c = cts[127], ga = gs_e[idx];
        float2 v0 = add2(c, ga), v1 = add2(c, gprev);
        if (127 < i0) mL0 = max2(mL0, v0); else mR0 = max2(mR0, v0);
        if (127 < i1) mL1 = max2(mL1, v1); else mR1 = max2(mR1, v1);
    }

    float2 zf = make_float2(0.0f, 0.0f);
    float* dst = z ? d_poolB : d_poolA;
    if (t < 127) {
        float* p0 = dst + (b*S + i0)*(2*H) + 2*hp;
        *(float2*)(p0)     = max2(mL0, zf);
        *(float2*)(p0 + H) = max2(mR0, zf);
        float* p1 = dst + (b*S + i1)*(2*H) + 2*hp;
        *(float2*)(p1)     = max2(mL1, zf);
        *(float2*)(p1 + H) = max2(mR1, zf);
    }
}

// ---------------- final logits: warp per (b,s), max of zone partials ----------------
__global__ __launch_bounds__(256) void final_kernel(const float* fc_b, float* out) {
    int gw = (blockIdx.x * 256 + threadIdx.x) >> 5;
    int lane = threadIdx.x & 31;
    int s = gw & (S-1);
    float* o = out + gw * L;
    if (s == 0 || s == S-1) {
        o[lane] = 0.0f;
        if (lane < 2) o[lane + 32] = (lane == 1) ? 1.0f : 0.0f;
        return;
    }
    const float* prA = d_poolA + gw * (2*H);
    const float* prB = d_poolB + gw * (2*H);
    const float* Wl = d_fcW2t + lane * 400;
    float a0 = 0.f, a1 = 0.f, a2 = 0.f, a3 = 0.f;
    #pragma unroll 4
    for (int c = 0; c < 400; c += 4) {
        float4 pa = *(const float4*)(prA + c);
        float4 pb = *(const float4*)(prB + c);
        float4 wv = *(const float4*)(Wl + c);
        a0 += fmaxf(pa.x, pb.x) * wv.x;
        a1 += fmaxf(pa.y, pb.y) * wv.y;
        a2 += fmaxf(pa.z, pb.z) * wv.z;
        a3 += fmaxf(pa.w, pb.w) * wv.w;
    }
    float acc0 = (a0 + a1) + (a2 + a3) + fc_b[lane];
    acc0 += d_Y[(gw-1)*NP + 600 + lane]
          + d_Y[gw*NP     + 634 + lane]
          + d_Y[(gw+1)*NP + 668 + lane];
    o[lane] = acc0;

    const float* W32 = d_fcW2t + 32 * 400;
    const float* W33 = d_fcW2t + 33 * 400;
    float r32 = 0.f, r33 = 0.f;
    #pragma unroll
    for (int c = lane; c < 400; c += 32) {
        float p = fmaxf(prA[c], prB[c]);
        r32 += p * W32[c];
        r33 += p * W33[c];
    }
    #pragma unroll
    for (int off = 16; off > 0; off >>= 1) {
        r32 += __shfl_xor_sync(0xFFFFFFFF, r32, off);
        r33 += __shfl_xor_sync(0xFFFFFFFF, r33, off);
    }
    if (lane < 2) {
        float r = (lane == 0) ? r32 : r33;
        r += fc_b[32 + lane]
           + d_Y[(gw-1)*NP + 632 + lane]
           + d_Y[gw*NP     + 666 + lane]
           + d_Y[(gw+1)*NP + 700 + lane];
        o[32 + lane] = r;
    }
}

extern "C" void kernel_launch(void* const* d_in, const int* in_sizes, int n_in,
                              void* d_out, int out_size) {
    const int*   inputs   = (const int*)d_in[0];
    const float* word_emb = (const float*)d_in[1];
    const float* pf_emb   = (const float*)d_in[2];
    const float* conv_W   = (const float*)d_in[3];
    const float* conv_b   = (const float*)d_in[4];
    const float* fc_W     = (const float*)d_in[5];
    const float* fc_b     = (const float*)d_in[6];
    float* out = (float*)d_out;

    prepA_kernel<<<M, 192>>>(inputs, word_emb);           // launch 0
    prepB_kernel<<<361, 256>>>(conv_W, fc_W, pf_emb);     // launch 1

    dim3 ggrid(M/128, NP/64);
    gemm_kernel<<<ggrid, 512>>>();                        // launch 2

    dim3 pgrid(H/2, B, 2);
    pool_kernel<<<pgrid, 128>>>(conv_b);                  // launch 3 (profiled slot)

    final_kernel<<<256, 256>>>(fc_b, out);                // launch 4
}

// round 7
// speedup vs baseline: 1.0414x; 1.0166x over previous
#include <cuda_runtime.h>
#include <cuda_bf16.h>

#define E   300
#define P   5
#define H   200
#define S   256
#define L   34
#define B   8
#define KPP 160          // kpairs per A row (K = 320 padded)
#define NP  704          // N padded (702 -> 704)
#define M   (B*S)        // 2048
#define FCK (3*E + 2*H)  // 1300

// ---------------- scratch ----------------
__device__ __align__(16) unsigned d_Ahp[M*KPP];   // A hi plane, bf16x2 [row][kpair]
__device__ __align__(16) unsigned d_Alp[M*KPP];   // A lo plane
__device__ __align__(16) unsigned d_Whp[KPP*NP];  // W hi plane, bf16x2 [kpair][n]
__device__ __align__(16) unsigned d_Wlp[KPP*NP];  // W lo plane
__device__ __align__(16) float d_Y[M*NP];
__device__ __align__(16) float d_g4[50*2048];     // [cquad][plane][q][4ch] : g in plane-quad layout
__device__ __align__(16) float d_gB0[S*H];        // [i][h]
__device__ __align__(16) float d_gB255[S*H];      // [i][h]
__device__ __align__(16) float d_poolA[M*2*H];    // zone-0 partial (relu'd)
__device__ __align__(16) float d_poolB[M*2*H];    // zone-1 partial (relu'd)
__device__ __align__(16) float d_fcW2t[L*400];    // [l][c]

// ---------------- helpers ----------------
union F2U { float2 f; unsigned long long u; };
__device__ __forceinline__ float2 add2(float2 a, float2 b) {
    F2U ua, ub, uc;
    ua.f = a; ub.f = b;
    asm("add.rn.f32x2 %0, %1, %2;" : "=l"(uc.u) : "l"(ua.u), "l"(ub.u));
    return uc.f;
}
__device__ __forceinline__ float4 add44(float4 a, float4 b) {
    float2 lo = add2(make_float2(a.x, a.y), make_float2(b.x, b.y));
    float2 hi = add2(make_float2(a.z, a.w), make_float2(b.z, b.w));
    return make_float4(lo.x, lo.y, hi.x, hi.y);
}
__device__ __forceinline__ float4 max44(float4 a, float4 b) {
    return make_float4(fmaxf(a.x, b.x), fmaxf(a.y, b.y), fmaxf(a.z, b.z), fmaxf(a.w, b.w));
}
__device__ __forceinline__ unsigned pk2(float a, float b) {
    __nv_bfloat162 t = __floats2bfloat162_rn(a, b);
    return *reinterpret_cast<unsigned*>(&t);
}
__device__ __forceinline__ float bhi(float x) {
    return __bfloat162float(__float2bfloat16(x));
}
__device__ __forceinline__ void mma_bf16(float* d, const unsigned* a, const unsigned* b) {
    asm volatile("mma.sync.aligned.m16n8k16.row.col.f32.bf16.bf16.f32 "
        "{%0,%1,%2,%3},{%4,%5,%6,%7},{%8,%9},{%0,%1,%2,%3};\n"
        : "+f"(d[0]), "+f"(d[1]), "+f"(d[2]), "+f"(d[3])
        : "r"(a[0]), "r"(a[1]), "r"(a[2]), "r"(a[3]), "r"(b[0]), "r"(b[1]));
}
__device__ __forceinline__ void cpa16(unsigned dst, const void* src) {
    asm volatile("cp.async.ca.shared.global [%0], [%1], 16;\n" :: "r"(dst), "l"(src));
}

// ---------------- prepA: gather token embeddings into split bf16 planes ----------------
__global__ __launch_bounds__(192) void prepA_kernel(const int* in32, const float* word_emb) {
    int row = blockIdx.x;
    int lane = threadIdx.x & 31;
    int hw = in32[2*lane + 1];
    unsigned nz = __ballot_sync(0xffffffffu, hw != 0);
    long long tok = (nz == 0) ? ((const long long*)in32)[row]
                              : (long long)in32[row];
    int p = threadIdx.x;
    if (p >= KPP) return;
    const float* src = word_emb + tok * E;
    float x0 = 0.0f, x1 = 0.0f;
    int e = 2*p;
    if (e < E) {
        x0 = src[e];
        x1 = (e + 1 < E) ? src[e+1] : 0.0f;
    }
    float h0 = bhi(x0), h1 = bhi(x1);
    d_Ahp[row*KPP + p] = pk2(h0, h1);
    d_Alp[row*KPP + p] = pk2(x0 - h0, x1 - h1);
}

// ---------------- prepB: pack W planes + fcW2t + g-tables ----------------
__device__ __forceinline__ float wallv(int e, int c, const float* conv_W, const float* fc_W) {
    if (e >= E) return 0.0f;
    if (c < 600) {
        int k = c / 200, h = c % 200;
        return conv_W[h*((E+P)*3) + e*3 + k];
    }
    if (c < 702) {
        int cc = c - 600, k = cc / L, l = cc % L;
        return fc_W[l*FCK + 2*H + k*E + e];
    }
    return 0.0f;
}

__global__ void prepB_kernel(const float* conv_W, const float* fc_W, const float* pf_emb) {
    int blk = blockIdx.x;
    int tid = threadIdx.x;
    if (blk < 160) {                               // W planes, kpair = blk
        int kp = blk;
        for (int c = tid; c < NP; c += 256) {
            float v0 = wallv(2*kp,     c, conv_W, fc_W);
            float v1 = wallv(2*kp + 1, c, conv_W, fc_W);
            float h0 = bhi(v0), h1 = bhi(v1);
            d_Whp[kp*NP + c] = pk2(h0, h1);
            d_Wlp[kp*NP + c] = pk2(v0 - h0, v1 - h1);
        }
        return;
    }
    if (blk == 160) {                              // fcW2t[l][c]
        for (int idx = tid; idx < L*400; idx += 256) {
            int l = idx / 400, c = idx % 400;
            d_fcW2t[idx] = fc_W[l*FCK + c];
        }
        return;
    }
    int h = blk - 161;                             // 0..199 g-tables
    float w0[P], w1[P], w2[P];
    #pragma unroll
    for (int p = 0; p < P; p++) {
        const float* wp = conv_W + h*(E+P)*3 + (E+p)*3;
        w0[p] = wp[0]; w1[p] = wp[1]; w2[p] = wp[2];
    }
    for (int dd = tid; dd < 512; dd += 256) {
        int d = dd - 256;
        int i0 = abs(d-1); if (i0 > 255) i0 = 255;
        int i1 = abs(d);   if (i1 > 255) i1 = 255;
        int i2 = abs(d+1); if (i2 > 255) i2 = 255;
        float acc = 0.0f;
        #pragma unroll
        for (int p = 0; p < P; p++)
            acc += w0[p]*pf_emb[i0*P+p] + w1[p]*pf_emb[i1*P+p] + w2[p]*pf_emb[i2*P+p];
        // plane-quad layout: [cquad][plane=dd&3][q=dd>>2][4ch]
        d_g4[(h>>2)*2048 + (dd&3)*512 + (dd>>2)*4 + (h&3)] = acc;
    }
    if (tid >= 1 && tid <= 254) {
        int i = tid;
        float a0 = 0.0f, a255 = 0.0f;
        #pragma unroll
        for (int p = 0; p < P; p++) {
            a0   += w1[p]*pf_emb[i*P+p] + w2[p]*pf_emb[(i-1)*P+p];
            a255 += w0[p]*pf_emb[(254-i >= 0 ? 254-i : i-254)*P+p] + w1[p]*pf_emb[(255-i)*P+p];
        }
        d_gB0[i*H + h]   = a0;
        d_gB255[i*H + h] = a255;
    }
}

// ---------------- GEMM: cp.async double-buffered (unchanged from R6) ----------------
__global__ __launch_bounds__(512, 2) void gemm_kernel() {
    __shared__ unsigned Ah[2][128][20], Al[2][128][20];
    __shared__ unsigned Bh[2][16][72],  Bl[2][16][72];

    const int t = threadIdx.x, lane = t & 31, warp = t >> 5;
    const int wm = warp >> 1, wn = warp & 1;
    const int mBase = wm * 16, nBase = wn * 32;
    const int r0 = lane >> 2, c0 = lane & 3;

    float acc[4][4];
    #pragma unroll
    for (int ni = 0; ni < 4; ni++)
        #pragma unroll
        for (int q = 0; q < 4; q++) acc[ni][q] = 0.0f;

    const unsigned* Agh = d_Ahp + (size_t)blockIdx.x * 128 * KPP;
    const unsigned* Agl = d_Alp + (size_t)blockIdx.x * 128 * KPP;
    const unsigned* Bgh = d_Whp + blockIdx.y * 64;
    const unsigned* Bgl = d_Wlp + blockIdx.y * 64;

    const int am   = t >> 2;
    const int aseg = (t & 3) * 4;
    const int bpl  = t >> 8;
    const int bt   = t & 255;
    const int bk   = bt >> 4;
    const int bn4  = (bt & 15) * 4;

    unsigned sAh = (unsigned)__cvta_generic_to_shared(&Ah[0][am][aseg]);
    unsigned sAl = (unsigned)__cvta_generic_to_shared(&Al[0][am][aseg]);
    unsigned sB  = bpl ? (unsigned)__cvta_generic_to_shared(&Bl[0][bk][bn4])
                       : (unsigned)__cvta_generic_to_shared(&Bh[0][bk][bn4]);
    const unsigned* Bgp = bpl ? Bgl : Bgh;
    const unsigned A_ST = 128*20*4;
    const unsigned B_ST = 16*72*4;

    {
        cpa16(sAh, Agh + am*KPP + aseg);
        cpa16(sAl, Agl + am*KPP + aseg);
        cpa16(sB,  Bgp + bk*NP + bn4);
        asm volatile("cp.async.commit_group;\n");
    }

    #pragma unroll 1
    for (int ch = 0; ch < 10; ch++) {
        int st = ch & 1;
        if (ch < 9) {
            int kc = (ch + 1) * 16;
            int st1 = st ^ 1;
            cpa16(sAh + st1*A_ST, Agh + am*KPP + kc + aseg);
            cpa16(sAl + st1*A_ST, Agl + am*KPP + kc + aseg);
            cpa16(sB  + st1*B_ST, Bgp + (kc + bk)*NP + bn4);
            asm volatile("cp.async.commit_group;\n");
            asm volatile("cp.async.wait_group 1;\n");
        } else {
            asm volatile("cp.async.wait_group 0;\n");
        }
        __syncthreads();

        #pragma unroll
        for (int ks = 0; ks < 2; ks++) {
            int p0 = ks*8 + c0;
            int mr = mBase + r0;
            unsigned ah[4], al[4];
            ah[0] = Ah[st][mr][p0];     al[0] = Al[st][mr][p0];
            ah[1] = Ah[st][mr+8][p0];   al[1] = Al[st][mr+8][p0];
            ah[2] = Ah[st][mr][p0+4];   al[2] = Al[st][mr][p0+4];
            ah[3] = Ah[st][mr+8][p0+4]; al[3] = Al[st][mr+8][p0+4];
            unsigned bh[4][2], bl[4][2];
            #pragma unroll
            for (int ni = 0; ni < 4; ni++) {
                int n = nBase + ni*8 + r0;
                bh[ni][0] = Bh[st][p0][n];   bl[ni][0] = Bl[st][p0][n];
                bh[ni][1] = Bh[st][p0+4][n]; bl[ni][1] = Bl[st][p0+4][n];
            }
            #pragma unroll
            for (int ni = 0; ni < 4; ni++) {
                mma_bf16(acc[ni], ah, bh[ni]);
                mma_bf16(acc[ni], al, bh[ni]);
                mma_bf16(acc[ni], ah, bl[ni]);
            }
        }
        __syncthreads();
    }

    float* Yg = d_Y + (size_t)(blockIdx.x*128)*NP + blockIdx.y*64;
    int mr = mBase + r0;
    #pragma unroll
    for (int ni = 0; ni < 4; ni++) {
        int nc = nBase + ni*8 + 2*c0;
        *(float2*)(Yg + mr*NP + nc)     = make_float2(acc[ni][0], acc[ni][1]);
        *(float2*)(Yg + (mr+8)*NP + nc) = make_float2(acc[ni][2], acc[ni][3]);
    }
}

// ---------------- fused ct + max-plus pooling: 4 centers x 4 channels/thread ----------------
__device__ __forceinline__ float4 compute_ct4(int b, int j, int cb, float4 v) {
    int row = b*S + j;
    v = add44(v, *(const float4*)&d_Y[row*NP + 200 + cb]);
    if (j > 0)   v = add44(v, *(const float4*)&d_Y[(row-1)*NP + cb]);
    if (j < S-1) v = add44(v, *(const float4*)&d_Y[(row+1)*NP + 400 + cb]);
    return v;
}

__global__ __launch_bounds__(128) void pool_kernel(const float* conv_b) {
    int bx = blockIdx.x;            // channel octet 0..24
    int b  = blockIdx.y;
    int z  = blockIdx.z;            // j-zone
    __shared__ float4 gp[2][4][128];   // [group][plane][q]
    __shared__ float4 cts[2][128];
    int t = threadIdx.x, g = t >> 6, lt = t & 63;
    int cb = bx*8 + g*4;            // channel base

    // fill g planes: contiguous copy of this cquad's 8KB
    const float4* gsrc = (const float4*)d_g4 + (bx*2 + g)*512;
    float4* gdst = &gp[g][0][0];
    #pragma unroll
    for (int r = 0; r < 8; r++)
        gdst[lt + 64*r] = gsrc[lt + 64*r];

    float4 cb4 = *(const float4*)&conv_b[cb];
    cts[g][lt]      = compute_ct4(b, z*128 + lt, cb, cb4);
    cts[g][lt + 64] = compute_ct4(b, z*128 + lt + 64, cb, cb4);
    __syncthreads();

    const int ifirst = 4*lt + 1;
    const float NEG = -1e30f;
    float4 neg4 = make_float4(NEG, NEG, NEG, NEG);
    float4 mL[4], mR[4];
    if (z == 0) {
        float4 c0 = cts[g][0];
        #pragma unroll
        for (int k = 0; k < 4; k++) {
            int ie = min(ifirst + k, 254);
            mL[k] = add44(c0, *(const float4*)&d_gB0[ie*H + cb]);
            mR[k] = neg4;
        }
    } else {
        float4 c255 = cts[g][127];
        #pragma unroll
        for (int k = 0; k < 4; k++) {
            int ie = min(ifirst + k, 254);
            mR[k] = add44(c255, *(const float4*)&d_gB255[ie*H + cb]);
            mL[k] = neg4;
        }
    }

    const int jstart = z ? 128 : 1;
    const int jend   = z ? 254 : 127;
    // window: w3 = newest (dd = j+255-4lt); center k uses w[3-k]
    float4 w0, w1, w2, w3;
    {
        int dbase = jstart + 252 - 4*lt;
        int d0 = dbase;     w0 = gp[g][d0 & 3][d0 >> 2];
        int d1 = dbase + 1; w1 = gp[g][d1 & 3][d1 >> 2];
        int d2 = dbase + 2; w2 = gp[g][d2 & 3][d2 >> 2];
        int d3 = dbase + 3; w3 = gp[g][d3 & 3][d3 >> 2];
    }

    bool mixed = z ? (lt >= 32) : (lt < 32);
    if (mixed) {
        #pragma unroll 4
        for (int j = jstart; j <= jend; j++) {
            float4 c = cts[g][j - z*128];
            int t4 = j - 4*lt;           // left iff t4 <= k
            float4 v;
            v = add44(c, w3); if (t4 <= 0) mL[0] = max44(mL[0], v); else mR[0] = max44(mR[0], v);
            v = add44(c, w2); if (t4 <= 1) mL[1] = max44(mL[1], v); else mR[1] = max44(mR[1], v);
            v = add44(c, w1); if (t4 <= 2) mL[2] = max44(mL[2], v); else mR[2] = max44(mR[2], v);
            v = add44(c, w0); if (t4 <= 3) mL[3] = max44(mL[3], v); else mR[3] = max44(mR[3], v);
            w0 = w1; w1 = w2; w2 = w3;
            int dn = j + 256 - 4*lt;
            w3 = gp[g][dn & 3][dn >> 2];
        }
    } else {
        // uniform side: z=0 -> all-left, z=1 -> all-right
        float4 mU[4];
        #pragma unroll
        for (int k = 0; k < 4; k++) mU[k] = z ? mR[k] : mL[k];
        #pragma unroll 4
        for (int j = jstart; j <= jend; j++) {
            float4 c = cts[g][j - z*128];
            mU[0] = max44(mU[0], add44(c, w3));
            mU[1] = max44(mU[1], add44(c, w2));
            mU[2] = max44(mU[2], add44(c, w1));
            mU[3] = max44(mU[3], add44(c, w0));
            w0 = w1; w1 = w2; w2 = w3;
            int dn = j + 256 - 4*lt;
            w3 = gp[g][dn & 3][dn >> 2];
        }
        #pragma unroll
        for (int k = 0; k < 4; k++) { if (z) mR[k] = mU[k]; else mL[k] = mU[k]; }
    }

    float4 z4 = make_float4(0.f, 0.f, 0.f, 0.f);
    float* dst = z ? d_poolB : d_poolA;
    #pragma unroll
    for (int k = 0; k < 4; k++) {
        int i = ifirst + k;
        if (i <= 254) {
            *(float4*)&dst[(b*S + i)*(2*H) + cb]     = max44(mL[k], z4);
            *(float4*)&dst[(b*S + i)*(2*H) + H + cb] = max44(mR[k], z4);
        }
    }
}

// ---------------- final logits: warp per (b,s), max of zone partials ----------------
__global__ __launch_bounds__(256) void final_kernel(const float* fc_b, float* out) {
    int gw = (blockIdx.x * 256 + threadIdx.x) >> 5;
    int lane = threadIdx.x & 31;
    int s = gw & (S-1);
    float* o = out + gw * L;
    if (s == 0 || s == S-1) {
        o[lane] = 0.0f;
        if (lane < 2) o[lane + 32] = (lane == 1) ? 1.0f : 0.0f;
        return;
    }
    const float* prA = d_poolA + gw * (2*H);
    const float* prB = d_poolB + gw * (2*H);
    const float* Wl = d_fcW2t + lane * 400;
    float a0 = 0.f, a1 = 0.f, a2 = 0.f, a3 = 0.f;
    #pragma unroll 4
    for (int c = 0; c < 400; c += 4) {
        float4 pa = *(const float4*)(prA + c);
        float4 pb = *(const float4*)(prB + c);
        float4 wv = *(const float4*)(Wl + c);
        a0 += fmaxf(pa.x, pb.x) * wv.x;
        a1 += fmaxf(pa.y, pb.y) * wv.y;
        a2 += fmaxf(pa.z, pb.z) * wv.z;
        a3 += fmaxf(pa.w, pb.w) * wv.w;
    }
    float acc0 = (a0 + a1) + (a2 + a3) + fc_b[lane];
    acc0 += d_Y[(gw-1)*NP + 600 + lane]
          + d_Y[gw*NP     + 634 + lane]
          + d_Y[(gw+1)*NP + 668 + lane];
    o[lane] = acc0;

    const float* W32 = d_fcW2t + 32 * 400;
    const float* W33 = d_fcW2t + 33 * 400;
    float r32 = 0.f, r33 = 0.f;
    #pragma unroll
    for (int c = lane; c < 400; c += 32) {
        float p = fmaxf(prA[c], prB[c]);
        r32 += p * W32[c];
        r33 += p * W33[c];
    }
    #pragma unroll
    for (int off = 16; off > 0; off >>= 1) {
        r32 += __shfl_xor_sync(0xFFFFFFFF, r32, off);
        r33 += __shfl_xor_sync(0xFFFFFFFF, r33, off);
    }
    if (lane < 2) {
        float r = (lane == 0) ? r32 : r33;
        r += fc_b[32 + lane]
           + d_Y[(gw-1)*NP + 632 + lane]
           + d_Y[gw*NP     + 666 + lane]
           + d_Y[(gw+1)*NP + 700 + lane];
        o[32 + lane] = r;
    }
}

extern "C" void kernel_launch(void* const* d_in, const int* in_sizes, int n_in,
                              void* d_out, int out_size) {
    const int*   inputs   = (const int*)d_in[0];
    const float* word_emb = (const float*)d_in[1];
    const float* pf_emb   = (const float*)d_in[2];
    const float* conv_W   = (const float*)d_in[3];
    const float* conv_b   = (const float*)d_in[4];
    const float* fc_W     = (const float*)d_in[5];
    const float* fc_b     = (const float*)d_in[6];
    float* out = (float*)d_out;

    prepA_kernel<<<M, 192>>>(inputs, word_emb);           // launch 0
    prepB_kernel<<<361, 256>>>(conv_W, fc_W, pf_emb);     // launch 1

    dim3 ggrid(M/128, NP/64);
    gemm_kernel<<<ggrid, 512>>>();                        // launch 2

    dim3 pgrid(25, B, 2);
    pool_kernel<<<pgrid, 128>>>(conv_b);                  // launch 3 (profiled slot)

    final_kernel<<<256, 256>>>(fc_b, out);                // launch 4
}